// round 7
// baseline (speedup 1.0000x reference)
#include <cuda_runtime.h>
#include <cuda_bf16.h>
#include <cstdint>

#define T_FRAMES 11
#define HID 1024
#define NTOT 1536
#define LN_EPS 1e-5f

// ===================== device scratch =====================
#define MROWS_MAX (8192L * T_FRAMES)          // 90112
__device__ __nv_bfloat16 g_h_hi[MROWS_MAX * HID];
__device__ __nv_bfloat16 g_W_hi[NTOT * HID];
__device__ float g_w2p[8][HID * HID];          // split-K partials
__device__ float g_bias[NTOT];
__device__ __nv_bfloat16 g_qk[MROWS_MAX * 512];  // Q|K outputs, bf16
__device__ float g_x[MROWS_MAX * HID];           // X outputs, fp32

// ===================== PTX helpers (base sm_80+ features only) =====================
__device__ __forceinline__ uint32_t smem_u32(const void* p) {
    uint32_t a;
    asm("{ .reg .u64 t; cvta.to.shared.u64 t, %1; cvt.u32.u64 %0, t; }" : "=r"(a) : "l"(p));
    return a;
}
__device__ __forceinline__ void cp16(uint32_t dst, const void* src) {
    asm volatile("cp.async.cg.shared.global [%0], [%1], 16;" :: "r"(dst), "l"(src));
}
#define CP_COMMIT() asm volatile("cp.async.commit_group;" ::: "memory")
#define CP_WAIT1()  asm volatile("cp.async.wait_group 1;" ::: "memory")

__device__ __forceinline__ void ldsm4(uint32_t& r0, uint32_t& r1, uint32_t& r2, uint32_t& r3,
                                      uint32_t addr) {
    asm volatile("ldmatrix.sync.aligned.m8n8.x4.shared.b16 {%0,%1,%2,%3}, [%4];"
                 : "=r"(r0), "=r"(r1), "=r"(r2), "=r"(r3) : "r"(addr));
}
__device__ __forceinline__ void mma16816(float* c, const uint32_t* a, const uint32_t* b) {
    asm volatile(
        "mma.sync.aligned.m16n8k16.row.col.f32.bf16.bf16.f32 "
        "{%0,%1,%2,%3}, {%4,%5,%6,%7}, {%8,%9}, {%0,%1,%2,%3};"
        : "+f"(c[0]), "+f"(c[1]), "+f"(c[2]), "+f"(c[3])
        : "r"(a[0]), "r"(a[1]), "r"(a[2]), "r"(a[3]), "r"(b[0]), "r"(b[1]));
}

// ===================== h -> bf16 =====================
__global__ __launch_bounds__(256) void convert_h_kernel(const float* __restrict__ h) {
    long i = (long)blockIdx.x * 256 + threadIdx.x; // over M*HID/4 float4s
    float4 v = ((const float4*)h)[i];
    union { __nv_bfloat162 b[2]; uint2 u; } ph;
    ph.b[0] = __floats2bfloat162_rn(v.x, v.y);
    ph.b[1] = __floats2bfloat162_rn(v.z, v.w);
    ((uint2*)g_h_hi)[i] = ph.u;
}

// ===================== W2 = Wo @ Wv, split-K x8 =====================
__global__ __launch_bounds__(256) void w2_part_kernel(const float* __restrict__ Wo,
                                                      const float* __restrict__ Wv) {
    __shared__ float As[64][16];
    __shared__ float Bs[16][64];
    const int tid = threadIdx.x;
    const int tx = tid & 15, ty = tid >> 4;
    const int row0 = blockIdx.y * 64, col0 = blockIdx.x * 64;
    const int kbase = blockIdx.z * 128;
    float acc[4][4] = {};
    for (int k0 = kbase; k0 < kbase + 128; k0 += 16) {
        for (int i = tid; i < 1024; i += 256) {
            As[i >> 4][i & 15] = Wo[(size_t)(row0 + (i >> 4)) * HID + k0 + (i & 15)];
            Bs[i >> 6][i & 63] = Wv[(size_t)(k0 + (i >> 6)) * HID + col0 + (i & 63)];
        }
        __syncthreads();
        #pragma unroll
        for (int kk = 0; kk < 16; kk++) {
            float a0 = As[ty*4+0][kk], a1 = As[ty*4+1][kk], a2 = As[ty*4+2][kk], a3 = As[ty*4+3][kk];
            float4 b = *(const float4*)&Bs[kk][tx*4];
            acc[0][0]=fmaf(a0,b.x,acc[0][0]); acc[0][1]=fmaf(a0,b.y,acc[0][1]); acc[0][2]=fmaf(a0,b.z,acc[0][2]); acc[0][3]=fmaf(a0,b.w,acc[0][3]);
            acc[1][0]=fmaf(a1,b.x,acc[1][0]); acc[1][1]=fmaf(a1,b.y,acc[1][1]); acc[1][2]=fmaf(a1,b.z,acc[1][2]); acc[1][3]=fmaf(a1,b.w,acc[1][3]);
            acc[2][0]=fmaf(a2,b.x,acc[2][0]); acc[2][1]=fmaf(a2,b.y,acc[2][1]); acc[2][2]=fmaf(a2,b.z,acc[2][2]); acc[2][3]=fmaf(a2,b.w,acc[2][3]);
            acc[3][0]=fmaf(a3,b.x,acc[3][0]); acc[3][1]=fmaf(a3,b.y,acc[3][1]); acc[3][2]=fmaf(a3,b.z,acc[3][2]); acc[3][3]=fmaf(a3,b.w,acc[3][3]);
        }
        __syncthreads();
    }
    float* dst = g_w2p[blockIdx.z];
    #pragma unroll
    for (int i = 0; i < 4; i++)
        #pragma unroll
        for (int j = 0; j < 4; j++)
            dst[(size_t)(row0 + ty*4 + i) * HID + col0 + tx*4 + j] = acc[i][j];
}

// ===================== finalize W: reduce partials + convert all W to bf16 + biases ==
__global__ __launch_bounds__(256) void finalize_w_kernel(const float* __restrict__ Wq,
                                                         const float* __restrict__ Wk,
                                                         const float* __restrict__ bq,
                                                         const float* __restrict__ bk,
                                                         const float* __restrict__ Wo,
                                                         const float* __restrict__ bv,
                                                         const float* __restrict__ bo) {
    if (blockIdx.x < 1536) {
        int i = blockIdx.x * 256 + threadIdx.x;        // over 1536*1024/4 float4s
        int row = i >> 8, c4 = i & 255;
        float4 v;
        if (row < 256)      v = ((const float4*)(Wq + (size_t)row * HID))[c4];
        else if (row < 512) v = ((const float4*)(Wk + (size_t)(row - 256) * HID))[c4];
        else {
            size_t off = (size_t)(row - 512) * 256 + c4;
            v = ((const float4*)g_w2p[0])[off];
            #pragma unroll
            for (int z = 1; z < 8; z++) {
                float4 p = ((const float4*)g_w2p[z])[off];
                v.x += p.x; v.y += p.y; v.z += p.z; v.w += p.w;
            }
        }
        union { __nv_bfloat162 b[2]; uint2 u; } ph;
        ph.b[0] = __floats2bfloat162_rn(v.x, v.y);
        ph.b[1] = __floats2bfloat162_rn(v.z, v.w);
        ((uint2*)g_W_hi)[i] = ph.u;
        if (i < 128)
            ((float4*)g_bias)[i] = (i < 64) ? ((const float4*)bq)[i] : ((const float4*)bk)[i - 64];
    } else {
        int o = (blockIdx.x - 1536) * 256 + threadIdx.x;   // 0..1023
        float s = 0.f;
        for (int m = 0; m < HID; m += 4) {
            float4 w = *(const float4*)(Wo + (size_t)o * HID + m);
            float4 b = *(const float4*)(bv + m);
            s = fmaf(w.x,b.x,s); s = fmaf(w.y,b.y,s); s = fmaf(w.z,b.z,s); s = fmaf(w.w,b.w,s);
        }
        g_bias[512 + o] = s + bo[o];
    }
}

// ===================== mma.sync GEMM: [QK|X] = h * W^T + bias =====================
// CTA 128x128, 4 warps (2m x 2n), warp 64x64. BK=64, 3-stage cp.async,
// single __syncthreads per stage. 2 CTAs/SM.
#define BK 64
#define NKS (HID / BK)             // 16
#define MAT_B 16384                // 128 rows x 64 bf16 = 16KB per matrix
#define STAGE_B (2 * MAT_B)        // Ah|Bh = 32KB
#define GEMM_SMEM (3 * STAGE_B)    // 96KB

__device__ __forceinline__ uint32_t swz(uint32_t byte) {
    return byte ^ ((byte >> 3) & 0x70);
}

__global__ __launch_bounds__(128, 2) void gemm_kernel() {
    extern __shared__ __align__(1024) char sm[];
    const int tid = threadIdx.x, wid = tid >> 5, lane = tid & 31;
    const long m0 = (long)blockIdx.y * 128;
    const long n0 = (long)blockIdx.x * 128;
    const int m_w = (wid & 1) * 64;       // warp M offset
    const int n_w = (wid >> 1) * 64;      // warp N offset
    const uint32_t sb = smem_u32(sm);

    const __nv_bfloat16* __restrict__ Ah = g_h_hi + m0 * HID;
    const __nv_bfloat16* __restrict__ Bh = g_W_hi + n0 * HID;

    // cp.async mapping: 1024 16B-chunks per matrix per stage, 128 threads -> 8 each
    const int crow = tid >> 3;            // base row (we add i*16)
    const int ckc  = tid & 7;             // 16B chunk within 128B row

    #pragma unroll
    for (int s = 0; s < 2; s++) {          // prologue: stages 0,1
        uint32_t st = sb + s * STAGE_B;
        int ko = s * BK;
        #pragma unroll
        for (int i = 0; i < 8; i++) {
            int row = crow + i * 16;
            uint32_t sw = swz(row * 128 + ckc * 16);
            size_t go = (size_t)row * HID + ko + ckc * 8;
            cp16(st + sw,         Ah + go);
            cp16(st + MAT_B + sw, Bh + go);
        }
        CP_COMMIT();
    }

    float acc[4][8][4] = {};   // [mt][nt][reg]

    for (int ks = 0; ks < NKS; ks++) {
        CP_WAIT1();            // stage ks resident (<=1 group pending: ks+1)
        __syncthreads();       // also: everyone finished compute of ks-1

        if (ks + 2 < NKS) {    // load stage ks+2 into buffer (ks+2)%3 (held ks-1)
            uint32_t st2 = sb + ((ks + 2) % 3) * STAGE_B;
            int ko = (ks + 2) * BK;
            #pragma unroll
            for (int i = 0; i < 8; i++) {
                int row = crow + i * 16;
                uint32_t sw = swz(row * 128 + ckc * 16);
                size_t go = (size_t)row * HID + ko + ckc * 8;
                cp16(st2 + sw,         Ah + go);
                cp16(st2 + MAT_B + sw, Bh + go);
            }
        }
        CP_COMMIT();

        const uint32_t st = sb + (ks % 3) * STAGE_B;
        #pragma unroll
        for (int kk = 0; kk < BK / 16; kk++) {
            uint32_t ah[4][4], bh[8][2];
            #pragma unroll
            for (int mt = 0; mt < 4; mt++) {
                uint32_t byte = (uint32_t)(m_w + mt * 16 + (lane & 15)) * 128
                              + kk * 32 + ((lane >> 4) << 4);
                uint32_t sw = swz(byte);
                ldsm4(ah[mt][0], ah[mt][1], ah[mt][2], ah[mt][3], st + sw);
            }
            #pragma unroll
            for (int half = 0; half < 4; half++) {
                int grp = lane >> 3;
                uint32_t rowB = (uint32_t)(n_w + half * 16 + ((grp & 2) << 2) + (lane & 7));
                uint32_t byte = rowB * 128 + kk * 32 + ((grp & 1) << 4);
                uint32_t sw = swz(byte);
                ldsm4(bh[half*2][0], bh[half*2][1], bh[half*2+1][0], bh[half*2+1][1],
                      st + MAT_B + sw);
            }
            #pragma unroll
            for (int mt = 0; mt < 4; mt++)
                #pragma unroll
                for (int nt = 0; nt < 8; nt++)
                    mma16816(acc[mt][nt], ah[mt], bh[nt]);
        }
    }

    // epilogue: D + bias
    const int qrow = lane >> 2;            // 0..7
    const int qcol = 2 * (lane & 3);       // 0,2,4,6
    if (n0 < 512) {
        #pragma unroll
        for (int nt = 0; nt < 8; nt++) {
            const int col = (int)n0 + n_w + nt * 8 + qcol;
            const float2 bv = *(const float2*)(g_bias + col);
            #pragma unroll
            for (int mt = 0; mt < 4; mt++) {
                long r0 = m0 + m_w + mt * 16 + qrow;
                __nv_bfloat162 v0 = __floats2bfloat162_rn(acc[mt][nt][0] + bv.x,
                                                          acc[mt][nt][1] + bv.y);
                __nv_bfloat162 v1 = __floats2bfloat162_rn(acc[mt][nt][2] + bv.x,
                                                          acc[mt][nt][3] + bv.y);
                *(__nv_bfloat162*)(g_qk + r0 * 512 + col)       = v0;
                *(__nv_bfloat162*)(g_qk + (r0 + 8) * 512 + col) = v1;
            }
        }
    } else {
        #pragma unroll
        for (int nt = 0; nt < 8; nt++) {
            const int colb = (int)n0 + n_w + nt * 8 + qcol;
            const float2 bv = *(const float2*)(g_bias + colb);
            const int col = colb - 512;
            #pragma unroll
            for (int mt = 0; mt < 4; mt++) {
                long r0 = m0 + m_w + mt * 16 + qrow;
                float2 v0 = { acc[mt][nt][0] + bv.x, acc[mt][nt][1] + bv.y };
                float2 v1 = { acc[mt][nt][2] + bv.x, acc[mt][nt][3] + bv.y };
                *(float2*)(g_x + r0 * HID + col)       = v0;
                *(float2*)(g_x + (r0 + 8) * HID + col) = v1;
            }
        }
    }
}

// ===================== attention + softmax + residual + LN =====================
#define QK_STR 520
#define ATTN_SMEM (((11 * 1024 + 132) * 4) + (11 * QK_STR * 2))

__global__ __launch_bounds__(256) void attn_kernel(const float* __restrict__ h,
                                                   const float* __restrict__ gamma,
                                                   const float* __restrict__ beta,
                                                   const float* __restrict__ screen_d, int n_screen,
                                                   const float* __restrict__ scale,
                                                   float* __restrict__ out) {
    extern __shared__ float sa[];
    float* xs = sa;                          // [11][1024]
    float* sc = sa + 11 * 1024;              // [11][12]
    __nv_bfloat16* qk = (__nv_bfloat16*)(sa + 11 * 1024 + 132);  // [11][520]
    const int tid = threadIdx.x;
    const long b = blockIdx.x;
    const __nv_bfloat16* __restrict__ qkb = g_qk + b * T_FRAMES * 512;
    const float* __restrict__ xb = g_x + b * T_FRAMES * HID;
    const float* __restrict__ hb = h + b * T_FRAMES * HID;

    for (int idx = tid; idx < 11 * 64; idx += 256) {
        int r = idx >> 6, c = idx & 63;
        *((uint4*)(qk + r * QK_STR) + c) = ((const uint4*)(qkb + r * 512))[c];
    }
    __syncthreads();

    const float scl = scale[0];
    if (tid < 121) {
        int i = tid / 11, j = tid - i * 11;
        const __nv_bfloat162* q2 = (const __nv_bfloat162*)(qk + i * QK_STR);
        const __nv_bfloat162* k2 = (const __nv_bfloat162*)(qk + j * QK_STR + 256);
        float s = 0.f;
        #pragma unroll 16
        for (int k = 0; k < 128; k++) {
            float2 a = __bfloat1622float2(q2[k]);
            float2 bb = __bfloat1622float2(k2[k]);
            s = fmaf(a.x, bb.x, s);
            s = fmaf(a.y, bb.y, s);
        }
        float r = fabsf((float)(i - j));
        float rr2 = r * r + 1e-6f;
        float wsum = 0.f, sg = 1.f;
        for (int kk = 0; kk < n_screen; kk++) {
            float d = screen_d[kk];
            wsum += sg * rsqrtf(d * d + rr2);
            sg = -sg;
        }
        sc[i * 12 + j] = s * 0.0625f + wsum / (scl + 1e-6f);
    }
    __syncthreads();

    if (tid < T_FRAMES) {
        float* row = sc + tid * 12;
        float m = row[0];
        #pragma unroll
        for (int j = 1; j < 11; j++) m = fmaxf(m, row[j]);
        float sum = 0.f;
        #pragma unroll
        for (int j = 0; j < 11; j++) { float e = expf(row[j] - m); row[j] = e; sum += e; }
        float inv = 1.f / sum;
        #pragma unroll
        for (int j = 0; j < 11; j++) row[j] *= inv;
    }
    __syncthreads();

    #pragma unroll
    for (int it = 0; it < 4; it++) {
        int c = tid + it * 256;
        float xv[11];
        #pragma unroll
        for (int j = 0; j < 11; j++) xv[j] = xb[j * HID + c];
        #pragma unroll
        for (int i = 0; i < 11; i++) {
            float a = 0.f;
            #pragma unroll
            for (int j = 0; j < 11; j++) a = fmaf(sc[i * 12 + j], xv[j], a);
            xs[i * 1024 + c] = hb[i * HID + c] + a;
        }
    }
    __syncthreads();

    const int w = tid >> 5, lane = tid & 31;
    for (int rr = w; rr < T_FRAMES; rr += 8) {
        const float* xrow = xs + rr * 1024;
        float s = 0.f, s2 = 0.f;
        for (int c = lane * 4; c < HID; c += 128) {
            float4 v = *(const float4*)(xrow + c);
            s  += v.x + v.y + v.z + v.w;
            s2 += v.x*v.x + v.y*v.y + v.z*v.z + v.w*v.w;
        }
        #pragma unroll
        for (int o = 16; o > 0; o >>= 1) {
            s  += __shfl_xor_sync(0xffffffffu, s, o);
            s2 += __shfl_xor_sync(0xffffffffu, s2, o);
        }
        float mu = s * (1.f / HID);
        float var = s2 * (1.f / HID) - mu * mu;
        float rstd = rsqrtf(var + LN_EPS);
        float* orow = out + (b * T_FRAMES + rr) * HID;
        for (int c = lane * 4; c < HID; c += 128) {
            float4 v = *(const float4*)(xrow + c);
            float4 g = *(const float4*)(gamma + c);
            float4 bb = *(const float4*)(beta + c);
            float4 o4;
            o4.x = (v.x - mu) * rstd * g.x + bb.x;
            o4.y = (v.y - mu) * rstd * g.y + bb.y;
            o4.z = (v.z - mu) * rstd * g.z + bb.z;
            o4.w = (v.w - mu) * rstd * g.w + bb.w;
            *(float4*)(orow + c) = o4;
        }
    }
}

// ===================== launch =====================
extern "C" void kernel_launch(void* const* d_in, const int* in_sizes, int n_in,
                              void* d_out, int out_size) {
    const float* h        = (const float*)d_in[0];
    const float* Wq       = (const float*)d_in[1];
    const float* bq       = (const float*)d_in[2];
    const float* Wk       = (const float*)d_in[3];
    const float* bk       = (const float*)d_in[4];
    const float* Wv       = (const float*)d_in[5];
    const float* bv       = (const float*)d_in[6];
    const float* Wo       = (const float*)d_in[7];
    const float* bo       = (const float*)d_in[8];
    const float* gamma    = (const float*)d_in[9];
    const float* beta     = (const float*)d_in[10];
    const float* screen_d = (const float*)d_in[11];
    const float* scale    = (const float*)d_in[12];
    const int n_screen = in_sizes[11];
    const long B = in_sizes[0] / (T_FRAMES * HID);
    const long M = B * T_FRAMES;                    // 90112
    float* out = (float*)d_out;

    cudaFuncSetAttribute(gemm_kernel, cudaFuncAttributeMaxDynamicSharedMemorySize, GEMM_SMEM);
    cudaFuncSetAttribute(attn_kernel, cudaFuncAttributeMaxDynamicSharedMemorySize, ATTN_SMEM);

    convert_h_kernel<<<(unsigned)((M * HID / 4) / 256), 256>>>(h);
    w2_part_kernel<<<dim3(HID / 64, HID / 64, 8), 256>>>(Wo, Wv);
    finalize_w_kernel<<<1536 + 4, 256>>>(Wq, Wk, bq, bk, Wo, bv, bo);

    dim3 ggrid(NTOT / 128, (unsigned)(M / 128));
    gemm_kernel<<<ggrid, 128, GEMM_SMEM>>>();

    attn_kernel<<<(unsigned)B, 256, ATTN_SMEM>>>(h, gamma, beta, screen_d, n_screen, scale, out);
}